// round 1
// baseline (speedup 1.0000x reference)
#include <cuda_runtime.h>

// ---------------------------------------------------------------------------
// GraphConstruction: A[i,j] = all_k( ||patch_i[:,k]-patch_j[:,k]||_2 <= 7 )
// N = 4096 patches, 16x16 each. Augmented-18-row Gram formulation:
//   score_k(i,j) = sum_{r<16} P[i,r,k]*P[j,r,k] + 1*(12.25-0.5*sq_jk)
//                + (12.25-0.5*sq_ik)*1   >= 0   <=>  d2 <= 49
// A[i,j] = (min_k score_k >= 0)
// ---------------------------------------------------------------------------

#define NP 4096
#define RAUG 18

// [k][r][n] layout, k<16, r<18, n<4096.  16*18*4096*4B = 4.5 MB scratch.
static __device__ float g_P[16 * RAUG * NP];

// ---------------- f32x2 packed-FMA helpers (sm_103a) -----------------------
__device__ __forceinline__ unsigned long long bcast2(float x) {
    unsigned long long r;
    asm("mov.b64 %0, {%1, %1};" : "=l"(r) : "f"(x));
    return r;
}
__device__ __forceinline__ void ffma2(unsigned long long& d,
                                      unsigned long long a,
                                      unsigned long long b) {
    asm("fma.rn.f32x2 %0, %1, %2, %3;" : "=l"(d) : "l"(a), "l"(b), "l"(d));
}
__device__ __forceinline__ float2 unpk2(unsigned long long v) {
    float2 f;
    asm("mov.b64 {%0, %1}, %2;" : "=f"(f.x), "=f"(f.y) : "l"(v));
    return f;
}
__device__ __forceinline__ void cp_async16(void* smem, const void* gmem) {
    unsigned s = (unsigned)__cvta_generic_to_shared(smem);
    asm volatile("cp.async.cg.shared.global [%0], [%1], 16;" :: "r"(s), "l"(gmem));
}
#define CP_COMMIT() asm volatile("cp.async.commit_group;")

// ---------------- prep 1: gather x into g_P rows 0..15 ---------------------
__global__ void prep1_kernel(const float* __restrict__ x) {
    int idx = blockIdx.x * blockDim.x + threadIdx.x;   // [0, 16*16*4096)
    int n  = idx & 4095;
    int rk = idx >> 12;          // k*16 + r  (constant per block)
    int k = rk >> 4;
    int r = rk & 15;
    int h = ((4 * (n & 15) + (r >> 2)) << 4) + (n >> 8);
    int w = ((16 * (r & 3) + k) << 4) + ((n >> 4) & 15);
    g_P[(k * RAUG + r) * NP + n] = x[h * 1024 + w];
}

// ---------------- prep 2: augmentation rows 16,17 ---------------------------
__global__ void prep2_kernel() {
    int idx = blockIdx.x * blockDim.x + threadIdx.x;   // [0, 16*4096)
    int n = idx & 4095;
    int k = idx >> 12;
    float s = 0.0f;
#pragma unroll
    for (int r = 0; r < 16; r++) {
        float v = g_P[(k * RAUG + r) * NP + n];
        s = fmaf(v, v, s);
    }
    g_P[(k * RAUG + 16) * NP + n] = 1.0f;
    g_P[(k * RAUG + 17) * NP + n] = 12.25f - 0.5f * s;
}

// ---------------- main: tiled pair kernel -----------------------------------
// Tile: 64 i x 128 j.  128 threads, each owns 8x8 pairs (j packed as f32x2).
// Triangle: run block iff ib <= 2*jb+1; write both A[i,j] and A[j,i].
__global__ void __launch_bounds__(128, 3) gram_kernel(float* __restrict__ A) {
    const int jb = blockIdx.x;           // 0..31   (j tile of 128)
    const int ib = blockIdx.y;           // 0..63   (i tile of 64)
    if (ib > 2 * jb + 1) return;

    __shared__ __align__(16) float sA[2][RAUG][64];
    __shared__ __align__(16) float sB[2][RAUG][128];

    const int tid = threadIdx.x;
    const int tx = tid & 15;             // j group
    const int ty = tid >> 4;             // i group (0..7)
    const int i0 = ib * 64;
    const int j0 = jb * 128;

    // ---- stage one k-slice into smem via cp.async ----
    auto issue = [&](int buf, int k) {
        // sA: 18 rows x 64 floats = 288 float4
#pragma unroll
        for (int idx = tid; idx < 288; idx += 128) {
            int r = idx >> 4, c = idx & 15;
            const float* src = &g_P[(k * RAUG + r) * NP + i0 + c * 4];
            cp_async16(&sA[buf][r][c * 4], src);
        }
        // sB: 18 rows x 128 floats = 576 float4 (rows 16/17 swapped)
#pragma unroll
        for (int idx = tid; idx < 576; idx += 128) {
            int r = idx >> 5, c = idx & 31;
            int rs = (r < 16) ? r : (33 - r);
            const float* src = &g_P[(k * RAUG + rs) * NP + j0 + c * 4];
            cp_async16(&sB[buf][r][c * 4], src);
        }
    };

    float mn[8][8];
#pragma unroll
    for (int a = 0; a < 8; a++)
#pragma unroll
        for (int b = 0; b < 8; b++) mn[a][b] = 1.0e30f;

    issue(0, 0);
    CP_COMMIT();

#pragma unroll 1
    for (int k = 0; k < 16; k++) {
        const int buf = k & 1;
        if (k < 15) {
            issue(buf ^ 1, k + 1);
            CP_COMMIT();
            asm volatile("cp.async.wait_group 1;");
        } else {
            asm volatile("cp.async.wait_group 0;");
        }
        __syncthreads();   // buf fully staged, visible to all

        unsigned long long acc[8][4];
#pragma unroll
        for (int a = 0; a < 8; a++)
#pragma unroll
            for (int b = 0; b < 4; b++) acc[a][b] = 0ULL;

#pragma unroll
        for (int r = 0; r < RAUG; r++) {
            float4 a0 = *(const float4*)&sA[buf][r][ty * 8];
            float4 a1 = *(const float4*)&sA[buf][r][ty * 8 + 4];
            ulonglong2 b0 = *(const ulonglong2*)&sB[buf][r][tx * 8];
            ulonglong2 b1 = *(const ulonglong2*)&sB[buf][r][tx * 8 + 4];
            unsigned long long bb[4] = {b0.x, b0.y, b1.x, b1.y};
            float av[8] = {a0.x, a0.y, a0.z, a0.w, a1.x, a1.y, a1.z, a1.w};
#pragma unroll
            for (int ii = 0; ii < 8; ii++) {
                unsigned long long aa = bcast2(av[ii]);
#pragma unroll
                for (int jj = 0; jj < 4; jj++) ffma2(acc[ii][jj], aa, bb[jj]);
            }
        }

        // fold this k's scores into running min
#pragma unroll
        for (int ii = 0; ii < 8; ii++)
#pragma unroll
            for (int jj = 0; jj < 4; jj++) {
                float2 v = unpk2(acc[ii][jj]);
                mn[ii][jj * 2]     = fminf(mn[ii][jj * 2], v.x);
                mn[ii][jj * 2 + 1] = fminf(mn[ii][jj * 2 + 1], v.y);
            }

        __syncthreads();   // compute(buf) done before next iter overwrites it
    }

    // threshold -> 0/1
#pragma unroll
    for (int ii = 0; ii < 8; ii++)
#pragma unroll
        for (int jj = 0; jj < 8; jj++)
            mn[ii][jj] = (mn[ii][jj] >= 0.0f) ? 1.0f : 0.0f;

    // direct tile write: A[i, j]
#pragma unroll
    for (int ii = 0; ii < 8; ii++) {
        size_t row = (size_t)(i0 + ty * 8 + ii) * 4096 + j0 + tx * 8;
        *(float4*)&A[row]     = make_float4(mn[ii][0], mn[ii][1], mn[ii][2], mn[ii][3]);
        *(float4*)&A[row + 4] = make_float4(mn[ii][4], mn[ii][5], mn[ii][6], mn[ii][7]);
    }
    // transposed write: A[j, i]  (i runs contiguous -> vectorized)
#pragma unroll
    for (int jj = 0; jj < 8; jj++) {
        size_t row = (size_t)(j0 + tx * 8 + jj) * 4096 + i0 + ty * 8;
        *(float4*)&A[row]     = make_float4(mn[0][jj], mn[1][jj], mn[2][jj], mn[3][jj]);
        *(float4*)&A[row + 4] = make_float4(mn[4][jj], mn[5][jj], mn[6][jj], mn[7][jj]);
    }
}

// ---------------------------------------------------------------------------
extern "C" void kernel_launch(void* const* d_in, const int* in_sizes, int n_in,
                              void* d_out, int out_size) {
    const float* x = (const float*)d_in[0];
    float* A = (float*)d_out;

    prep1_kernel<<<4096, 256>>>(x);        // 16*16*4096 elements
    prep2_kernel<<<256, 256>>>();          // 16*4096 elements
    gram_kernel<<<dim3(32, 64), 128>>>(A); // triangle of 64x128 tiles
}